// round 6
// baseline (speedup 1.0000x reference)
#include <cuda_runtime.h>

// Shape fixed by setup_inputs: x [8, 8192, 512] fp32, weight [512] fp32.
#define BB 8
#define TT 8192
#define CC 512
#define EPSF 1e-5f

#define THREADS 512              // 16 warps; 2 blocks/SM co-resident
#define FPB 32                   // frames per block -> 64 KB smem tile
#define BPB (TT / FPB)           // 256 blocks per batch
#define GRID (BB * BPB)          // 2048 blocks
#define FPW 2                    // frames per warp
#define SMEM_X_BYTES (FPB * CC * 4)

// Double-buffered published aggregates: low 32b = value, high 32b = flag.
// Statics zero-init, so parity 0 starts clean.
__device__ unsigned long long g_pubS1[2][GRID];
__device__ unsigned long long g_pubD[2][GRID];
__device__ int g_parity;
__device__ unsigned int g_done;

__device__ __forceinline__ void publish(unsigned long long* slot, float v) {
    *(volatile unsigned long long*)slot =
        (1ull << 32) | (unsigned long long)__float_as_uint(v);
}

// Warp-collective (warp 0): sum predecessor aggregates [0, kb) of this batch.
// kb <= 255 -> at most 8 slots per lane. First issue all loads independently
// (single L2 round-trip), then spin only on slots whose flag wasn't set.
__device__ __forceinline__ float lookback(unsigned long long* base, int kb, int lane) {
    unsigned long long u[8];
#pragma unroll
    for (int k = 0; k < 8; k++) {
        const int idx = lane + k * 32;
        u[k] = (idx < kb) ? *(volatile unsigned long long*)&base[idx]
                          : (1ull << 32);
    }
    float v = 0.f;
#pragma unroll
    for (int k = 0; k < 8; k++) {
        const int idx = lane + k * 32;
        if (idx < kb) {
            while (!(u[k] >> 32)) u[k] = *(volatile unsigned long long*)&base[idx];
            v += __uint_as_float((unsigned)u[k]);
        }
    }
#pragma unroll
    for (int o = 16; o > 0; o >>= 1) v += __shfl_xor_sync(0xffffffffu, v, o);
    return v;
}

__global__ void __launch_bounds__(THREADS, 2)
fused(const float* __restrict__ x, const float* __restrict__ w,
      float* __restrict__ out) {
    extern __shared__ float sX[];      // [FPB][CC] = 64 KB
    __shared__ float sS1[FPB];
    __shared__ float sQ[FPB];
    __shared__ float sMean[FPB];
    __shared__ float sInv[FPB];

    const int p = *(volatile int*)&g_parity;
    const int b = blockIdx.x / BPB;
    const int kb = blockIdx.x % BPB;
    const int wid = threadIdx.x >> 5;
    const int lane = threadIdx.x & 31;
    const size_t frame0 = (size_t)b * TT + (size_t)kb * FPB;

    // Clear the other parity's slots for the NEXT launch.
    if (threadIdx.x == 0) {
        *(volatile unsigned long long*)&g_pubS1[1 - p][blockIdx.x] = 0ull;
        *(volatile unsigned long long*)&g_pubD[1 - p][blockIdx.x] = 0ull;
    }

    // ---------------- Phase 1: front-batched loads, smem copy, reduce ------
    // Warp `wid` owns frames {2*wid, 2*wid+1}; lane handles 4 float4 each.
    const int f0 = wid * FPW;
    const float4* px0 = reinterpret_cast<const float4*>(x + (frame0 + f0) * CC);
    const float4* px1 = reinterpret_cast<const float4*>(x + (frame0 + f0 + 1) * CC);

    float4 r[2][4];
#pragma unroll
    for (int k = 0; k < 4; k++) r[0][k] = px0[lane + k * 32];
#pragma unroll
    for (int k = 0; k < 4; k++) r[1][k] = px1[lane + k * 32];

#pragma unroll
    for (int j = 0; j < FPW; j++) {
        float4* sx = reinterpret_cast<float4*>(sX + (f0 + j) * CC);
        float s = 0.f, q = 0.f;
#pragma unroll
        for (int k = 0; k < 4; k++) {
            float4 v = r[j][k];
            sx[lane + k * 32] = v;
            s += (v.x + v.y) + (v.z + v.w);
            q += v.x * v.x + v.y * v.y + v.z * v.z + v.w * v.w;
        }
#pragma unroll
        for (int o = 16; o > 0; o >>= 1) {
            s += __shfl_xor_sync(0xffffffffu, s, o);
            q += __shfl_xor_sync(0xffffffffu, q, o);
        }
        if (lane == 0) { sS1[f0 + j] = s; sQ[f0 + j] = q; }
    }
    __syncthreads();

    // ---------------- Warp 0: scan (1 frame/lane) + lookbacks --------------
    if (wid == 0) {
        const float s1 = sS1[lane];
        const float q = sQ[lane];

        float incl = s1;
#pragma unroll
        for (int o = 1; o < 32; o <<= 1) {
            float t = __shfl_up_sync(0xffffffffu, incl, o);
            if (lane >= o) incl += t;
        }
        if (lane == 31) publish(&g_pubS1[p][blockIdx.x], incl);
        const float excl1 = lookback(&g_pubS1[p][b * BPB], kb, lane);

        const int t = kb * FPB + lane;
        const float cnt = (float)(t + 1) * (float)CC;
        const float m = (excl1 + incl) / cnt;
        sMean[lane] = m;

        float D = q - 2.f * m * s1 + (float)CC * m * m;
        float inclD = D;
#pragma unroll
        for (int o = 1; o < 32; o <<= 1) {
            float tt = __shfl_up_sync(0xffffffffu, inclD, o);
            if (lane >= o) inclD += tt;
        }
        if (lane == 31) publish(&g_pubD[p][blockIdx.x], inclD);
        const float exclD = lookback(&g_pubD[p][b * BPB], kb, lane);

        const float var = (exclD + inclD) / cnt;
        sInv[lane] = rsqrtf(var + EPSF);
    }
    __syncthreads();

    // ---------------- Phase 3: normalize from smem -------------------------
#pragma unroll
    for (int j = 0; j < FPW; j++) {
        const int f = f0 + j;
        const float m = sMean[f];
        const float iv = sInv[f];
        const float4* sx = reinterpret_cast<const float4*>(sX + f * CC);
        const float4* w4 = reinterpret_cast<const float4*>(w);
        float4* po = reinterpret_cast<float4*>(out + (frame0 + f) * CC);
#pragma unroll
        for (int k = 0; k < 4; k++) {
            float4 v = sx[lane + k * 32];
            float4 wv = w4[lane + k * 32];   // L1-resident (512 floats, all blocks)
            float4 rr;
            rr.x = (v.x - m) * iv * wv.x;
            rr.y = (v.y - m) * iv * wv.y;
            rr.z = (v.z - m) * iv * wv.z;
            rr.w = (v.w - m) * iv * wv.w;
            __stcs(&po[lane + k * 32], rr);
        }
    }

    // ---------------- Epilogue: last block flips parity --------------------
    __syncthreads();
    if (threadIdx.x == 0) {
        __threadfence();
        unsigned int n = atomicAdd(&g_done, 1u);
        if (n == GRID - 1) {
            g_done = 0;
            g_parity = p ^ 1;
        }
    }
}

extern "C" void kernel_launch(void* const* d_in, const int* in_sizes, int n_in,
                              void* d_out, int out_size) {
    const float* x = (const float*)d_in[0];
    const float* w = (const float*)d_in[1];
    float* out = (float*)d_out;

    cudaFuncSetAttribute(fused, cudaFuncAttributeMaxDynamicSharedMemorySize,
                         SMEM_X_BYTES);
    fused<<<GRID, THREADS, SMEM_X_BYTES>>>(x, w, out);
}

// round 7
// speedup vs baseline: 1.3874x; 1.3874x over previous
#include <cuda_runtime.h>

// Shape fixed by setup_inputs: x [8, 8192, 512] fp32, weight [512] fp32.
#define BB 8
#define TT 8192
#define CC 512
#define EPSF 1e-5f

#define THREADS 512              // 16 warps; 2 blocks/SM -> all 256 resident
#define FPB 256                  // frames per block
#define BPB (TT / FPB)           // 32 blocks per batch
#define GRID (BB * BPB)          // 256 blocks, single wave
#define FPW (FPB / (THREADS/32)) // 16 frames per warp

// Double-buffered published aggregates: low 32b = value, high 32b = flag.
// Statics zero-init, so parity 0 starts clean.
__device__ unsigned long long g_pubS1[2][GRID];
__device__ unsigned long long g_pubD[2][GRID];
__device__ int g_parity;
__device__ unsigned int g_done;

__device__ __forceinline__ void publish(unsigned long long* slot, float v) {
    *(volatile unsigned long long*)slot =
        (1ull << 32) | (unsigned long long)__float_as_uint(v);
}

// Warp-collective (warp 0): sum predecessor aggregates [0, kb), kb <= 31.
__device__ __forceinline__ float lookback(unsigned long long* base, int kb, int lane) {
    float v = 0.f;
    if (lane < kb) {
        unsigned long long u;
        do {
            u = *(volatile unsigned long long*)&base[lane];
        } while (!(u >> 32));
        v = __uint_as_float((unsigned)u);
    }
#pragma unroll
    for (int o = 16; o > 0; o >>= 1) v += __shfl_xor_sync(0xffffffffu, v, o);
    return v;
}

__global__ void __launch_bounds__(THREADS, 2)
fused(const float* __restrict__ x, const float* __restrict__ w,
      float* __restrict__ out) {
    __shared__ float sS1[FPB];
    __shared__ float sQ[FPB];
    __shared__ float sI1[FPB];
    __shared__ float sID[FPB];
    __shared__ float sMean[FPB];
    __shared__ float sInv[FPB];
    __shared__ float sExcl1, sExclD;

    const int p = *(volatile int*)&g_parity;
    const int b = blockIdx.x / BPB;
    const int kb = blockIdx.x % BPB;
    const int wid = threadIdx.x >> 5;
    const int lane = threadIdx.x & 31;
    const size_t frame0 = (size_t)b * TT + (size_t)kb * FPB;

    // Clear the other parity's slots for the NEXT launch.
    if (threadIdx.x == 0) {
        *(volatile unsigned long long*)&g_pubS1[1 - p][blockIdx.x] = 0ull;
        *(volatile unsigned long long*)&g_pubD[1 - p][blockIdx.x] = 0ull;
    }

    // Weight registers (same 16 floats for every frame this lane touches).
    const float4* w4 = reinterpret_cast<const float4*>(w);
    float4 wv[4];
#pragma unroll
    for (int k = 0; k < 4; k++) wv[k] = w4[lane + k * 32];

    // ---------------- Phase 1: per-frame reductions (one warp per frame) ---
    for (int j = 0; j < FPW; j++) {
        const int f = wid * FPW + j;
        const float4* px = reinterpret_cast<const float4*>(x + (frame0 + f) * CC);
        float s = 0.f, q = 0.f;
#pragma unroll
        for (int k = 0; k < 4; k++) {
            float4 v = px[lane + k * 32];
            s += (v.x + v.y) + (v.z + v.w);
            q += v.x * v.x + v.y * v.y + v.z * v.z + v.w * v.w;
        }
#pragma unroll
        for (int o = 16; o > 0; o >>= 1) {
            s += __shfl_xor_sync(0xffffffffu, s, o);
            q += __shfl_xor_sync(0xffffffffu, q, o);
        }
        if (lane == 0) { sS1[f] = s; sQ[f] = q; }
    }
    __syncthreads();

    // ---------------- Block scan of S1 (warp 0, 8 values/lane) + lookback --
    if (wid == 0) {
        float v[8];
        float run = 0.f;
#pragma unroll
        for (int i = 0; i < 8; i++) { v[i] = sS1[lane * 8 + i]; run += v[i]; v[i] = run; }
        float incl = run;
#pragma unroll
        for (int o = 1; o < 32; o <<= 1) {
            float t = __shfl_up_sync(0xffffffffu, incl, o);
            if (lane >= o) incl += t;
        }
        float excl = incl - run;
#pragma unroll
        for (int i = 0; i < 8; i++) sI1[lane * 8 + i] = v[i] + excl;
        if (lane == 31) publish(&g_pubS1[p][blockIdx.x], incl);
        float e = lookback(&g_pubS1[p][b * BPB], kb, lane);
        if (lane == 0) sExcl1 = e;
    }
    __syncthreads();

    // ---------------- Phase 2a: per-frame mean and D -----------------------
    if (threadIdx.x < FPB) {
        const int t = kb * FPB + threadIdx.x;
        const float P = sExcl1 + sI1[threadIdx.x];
        const float cnt = (float)(t + 1) * (float)CC;
        const float m = P / cnt;
        sMean[threadIdx.x] = m;
        const float s1 = sS1[threadIdx.x];
        const float D = sQ[threadIdx.x] - 2.f * m * s1 + (float)CC * m * m;
        sQ[threadIdx.x] = D;  // reuse slot
    }
    __syncthreads();

    // ---------------- Block scan of D (warp 0) + lookback ------------------
    if (wid == 0) {
        float v[8];
        float run = 0.f;
#pragma unroll
        for (int i = 0; i < 8; i++) { v[i] = sQ[lane * 8 + i]; run += v[i]; v[i] = run; }
        float incl = run;
#pragma unroll
        for (int o = 1; o < 32; o <<= 1) {
            float t = __shfl_up_sync(0xffffffffu, incl, o);
            if (lane >= o) incl += t;
        }
        float excl = incl - run;
#pragma unroll
        for (int i = 0; i < 8; i++) sID[lane * 8 + i] = v[i] + excl;
        if (lane == 31) publish(&g_pubD[p][blockIdx.x], incl);
        float e = lookback(&g_pubD[p][b * BPB], kb, lane);
        if (lane == 0) sExclD = e;
    }
    __syncthreads();

    if (threadIdx.x < FPB) {
        const int t = kb * FPB + threadIdx.x;
        const float cnt = (float)(t + 1) * (float)CC;
        const float var = (sExclD + sID[threadIdx.x]) / cnt;
        sInv[threadIdx.x] = rsqrtf(var + EPSF);
    }
    __syncthreads();

    // ---------------- Phase 3: normalize, LIFO order, evict-first reads ----
    // Reverse order: most-recently-read frames are re-read first (still in
    // L2); __ldcs marks spent lines evict-first so they don't displace other
    // blocks' pending re-reads; __stcs keeps stores from polluting L2.
    for (int j = FPW - 1; j >= 0; j--) {
        const int f = wid * FPW + j;
        const float m = sMean[f];
        const float iv = sInv[f];
        const float* px = x + (frame0 + f) * CC;
        float4* po = reinterpret_cast<float4*>(out + (frame0 + f) * CC);
#pragma unroll
        for (int k = 3; k >= 0; k--) {
            float4 v = __ldcs(reinterpret_cast<const float4*>(px) + lane + k * 32);
            float4 r;
            r.x = (v.x - m) * iv * wv[k].x;
            r.y = (v.y - m) * iv * wv[k].y;
            r.z = (v.z - m) * iv * wv[k].z;
            r.w = (v.w - m) * iv * wv[k].w;
            __stcs(&po[lane + k * 32], r);
        }
    }

    // ---------------- Epilogue: last block flips parity --------------------
    __syncthreads();
    if (threadIdx.x == 0) {
        __threadfence();
        unsigned int n = atomicAdd(&g_done, 1u);
        if (n == GRID - 1) {
            g_done = 0;
            g_parity = p ^ 1;
        }
    }
}

extern "C" void kernel_launch(void* const* d_in, const int* in_sizes, int n_in,
                              void* d_out, int out_size) {
    const float* x = (const float*)d_in[0];
    const float* w = (const float*)d_in[1];
    float* out = (float*)d_out;
    fused<<<GRID, THREADS>>>(x, w, out);
}

// round 8
// speedup vs baseline: 1.4927x; 1.0759x over previous
#include <cuda_runtime.h>

// Shape fixed by setup_inputs: x [8, 8192, 512] fp32, weight [512] fp32.
#define BB 8
#define TT 8192
#define CC 512
#define EPSF 1e-5f

#define THREADS 256              // 8 warps; 4 blocks/SM -> 512 blocks, 1 wave
#define FPB 128                  // frames per block
#define BPB (TT / FPB)           // 64 blocks per batch
#define GRID (BB * BPB)          // 512 blocks
#define FPW (FPB / (THREADS/32)) // 16 frames per warp

// Double-buffered published aggregates: low 32b = value, high 32b = flag.
// Statics zero-init, so parity 0 starts clean.
__device__ unsigned long long g_pubS1[2][GRID];
__device__ unsigned long long g_pubD[2][GRID];
__device__ int g_parity;
__device__ unsigned int g_done;

__device__ __forceinline__ void publish(unsigned long long* slot, float v) {
    *(volatile unsigned long long*)slot =
        (1ull << 32) | (unsigned long long)__float_as_uint(v);
}

// Warp-collective (warp 0): sum predecessor aggregates [0, kb), kb <= 63.
__device__ __forceinline__ float lookback(unsigned long long* base, int kb, int lane) {
    float v = 0.f;
#pragma unroll
    for (int k = 0; k < 2; k++) {
        const int idx = lane + k * 32;
        if (idx < kb) {
            unsigned long long u;
            do {
                u = *(volatile unsigned long long*)&base[idx];
            } while (!(u >> 32));
            v += __uint_as_float((unsigned)u);
        }
    }
#pragma unroll
    for (int o = 16; o > 0; o >>= 1) v += __shfl_xor_sync(0xffffffffu, v, o);
    return v;
}

__global__ void __launch_bounds__(THREADS, 4)
fused(const float* __restrict__ x, const float* __restrict__ w,
      float* __restrict__ out) {
    __shared__ float sS1[FPB];
    __shared__ float sQ[FPB];
    __shared__ float sI1[FPB];
    __shared__ float sID[FPB];
    __shared__ float sMean[FPB];
    __shared__ float sInv[FPB];
    __shared__ float sExcl1, sExclD;

    const int p = *(volatile int*)&g_parity;
    const int b = blockIdx.x / BPB;
    const int kb = blockIdx.x % BPB;
    const int wid = threadIdx.x >> 5;
    const int lane = threadIdx.x & 31;
    const size_t frame0 = (size_t)b * TT + (size_t)kb * FPB;

    // Clear the other parity's slots for the NEXT launch.
    if (threadIdx.x == 0) {
        *(volatile unsigned long long*)&g_pubS1[1 - p][blockIdx.x] = 0ull;
        *(volatile unsigned long long*)&g_pubD[1 - p][blockIdx.x] = 0ull;
    }

    // ---------------- Phase 1: 2-frame batched loads, per-frame reduce -----
    for (int j = 0; j < FPW; j += 2) {
        const int f = wid * FPW + j;
        const float4* p0 = reinterpret_cast<const float4*>(x + (frame0 + f) * CC);
        const float4* p1 = reinterpret_cast<const float4*>(x + (frame0 + f + 1) * CC);
        float4 a[4], c[4];
#pragma unroll
        for (int k = 0; k < 4; k++) a[k] = p0[lane + k * 32];
#pragma unroll
        for (int k = 0; k < 4; k++) c[k] = p1[lane + k * 32];

        float s0 = 0.f, q0 = 0.f, s1 = 0.f, q1 = 0.f;
#pragma unroll
        for (int k = 0; k < 4; k++) {
            s0 += (a[k].x + a[k].y) + (a[k].z + a[k].w);
            q0 += a[k].x * a[k].x + a[k].y * a[k].y + a[k].z * a[k].z + a[k].w * a[k].w;
            s1 += (c[k].x + c[k].y) + (c[k].z + c[k].w);
            q1 += c[k].x * c[k].x + c[k].y * c[k].y + c[k].z * c[k].z + c[k].w * c[k].w;
        }
#pragma unroll
        for (int o = 16; o > 0; o >>= 1) {
            s0 += __shfl_xor_sync(0xffffffffu, s0, o);
            q0 += __shfl_xor_sync(0xffffffffu, q0, o);
            s1 += __shfl_xor_sync(0xffffffffu, s1, o);
            q1 += __shfl_xor_sync(0xffffffffu, q1, o);
        }
        if (lane == 0) {
            sS1[f] = s0; sQ[f] = q0;
            sS1[f + 1] = s1; sQ[f + 1] = q1;
        }
    }
    __syncthreads();

    // ---------------- Block scan of S1 (warp 0, 4 values/lane) + lookback --
    if (wid == 0) {
        float v[4];
        float run = 0.f;
#pragma unroll
        for (int i = 0; i < 4; i++) { v[i] = sS1[lane * 4 + i]; run += v[i]; v[i] = run; }
        float incl = run;
#pragma unroll
        for (int o = 1; o < 32; o <<= 1) {
            float t = __shfl_up_sync(0xffffffffu, incl, o);
            if (lane >= o) incl += t;
        }
        float excl = incl - run;
#pragma unroll
        for (int i = 0; i < 4; i++) sI1[lane * 4 + i] = v[i] + excl;
        if (lane == 31) publish(&g_pubS1[p][blockIdx.x], incl);
        float e = lookback(&g_pubS1[p][b * BPB], kb, lane);
        if (lane == 0) sExcl1 = e;
    }
    __syncthreads();

    // ---------------- Phase 2a: per-frame mean and D -----------------------
    if (threadIdx.x < FPB) {
        const int t = kb * FPB + threadIdx.x;
        const float P = sExcl1 + sI1[threadIdx.x];
        const float cnt = (float)(t + 1) * (float)CC;
        const float m = P / cnt;
        sMean[threadIdx.x] = m;
        const float s1 = sS1[threadIdx.x];
        const float D = sQ[threadIdx.x] - 2.f * m * s1 + (float)CC * m * m;
        sQ[threadIdx.x] = D;  // reuse slot
    }
    __syncthreads();

    // ---------------- Block scan of D (warp 0) + lookback ------------------
    if (wid == 0) {
        float v[4];
        float run = 0.f;
#pragma unroll
        for (int i = 0; i < 4; i++) { v[i] = sQ[lane * 4 + i]; run += v[i]; v[i] = run; }
        float incl = run;
#pragma unroll
        for (int o = 1; o < 32; o <<= 1) {
            float t = __shfl_up_sync(0xffffffffu, incl, o);
            if (lane >= o) incl += t;
        }
        float excl = incl - run;
#pragma unroll
        for (int i = 0; i < 4; i++) sID[lane * 4 + i] = v[i] + excl;
        if (lane == 31) publish(&g_pubD[p][blockIdx.x], incl);
        float e = lookback(&g_pubD[p][b * BPB], kb, lane);
        if (lane == 0) sExclD = e;
    }
    __syncthreads();

    if (threadIdx.x < FPB) {
        const int t = kb * FPB + threadIdx.x;
        const float cnt = (float)(t + 1) * (float)CC;
        const float var = (sExclD + sID[threadIdx.x]) / cnt;
        sInv[threadIdx.x] = rsqrtf(var + EPSF);
    }
    __syncthreads();

    // ---------------- Phase 3: normalize, 2 frames per iteration -----------
    for (int j = 0; j < FPW; j += 2) {
        const int f = wid * FPW + j;
        const float m0 = sMean[f], iv0 = sInv[f];
        const float m1 = sMean[f + 1], iv1 = sInv[f + 1];
        const float4* p0 = reinterpret_cast<const float4*>(x + (frame0 + f) * CC);
        const float4* p1 = reinterpret_cast<const float4*>(x + (frame0 + f + 1) * CC);
        const float4* w4 = reinterpret_cast<const float4*>(w);
        float4* o0 = reinterpret_cast<float4*>(out + (frame0 + f) * CC);
        float4* o1 = reinterpret_cast<float4*>(out + (frame0 + f + 1) * CC);

        float4 a[4], c[4];
#pragma unroll
        for (int k = 0; k < 4; k++) a[k] = p0[lane + k * 32];
#pragma unroll
        for (int k = 0; k < 4; k++) c[k] = p1[lane + k * 32];

#pragma unroll
        for (int k = 0; k < 4; k++) {
            float4 wv = w4[lane + k * 32];  // L1-hot
            float4 r0, r1;
            r0.x = (a[k].x - m0) * iv0 * wv.x;
            r0.y = (a[k].y - m0) * iv0 * wv.y;
            r0.z = (a[k].z - m0) * iv0 * wv.z;
            r0.w = (a[k].w - m0) * iv0 * wv.w;
            r1.x = (c[k].x - m1) * iv1 * wv.x;
            r1.y = (c[k].y - m1) * iv1 * wv.y;
            r1.z = (c[k].z - m1) * iv1 * wv.z;
            r1.w = (c[k].w - m1) * iv1 * wv.w;
            __stcs(&o0[lane + k * 32], r0);
            __stcs(&o1[lane + k * 32], r1);
        }
    }

    // ---------------- Epilogue: last block flips parity --------------------
    __syncthreads();
    if (threadIdx.x == 0) {
        __threadfence();
        unsigned int n = atomicAdd(&g_done, 1u);
        if (n == GRID - 1) {
            g_done = 0;
            g_parity = p ^ 1;
        }
    }
}

extern "C" void kernel_launch(void* const* d_in, const int* in_sizes, int n_in,
                              void* d_out, int out_size) {
    const float* x = (const float*)d_in[0];
    const float* w = (const float*)d_in[1];
    float* out = (float*)d_out;
    fused<<<GRID, THREADS>>>(x, w, out);
}

// round 9
// speedup vs baseline: 1.5536x; 1.0408x over previous
#include <cuda_runtime.h>

// Shape fixed by setup_inputs: x [8, 8192, 512] fp32, weight [512] fp32.
#define BB 8
#define TT 8192
#define CC 512
#define EPSF 1e-5f

#define THREADS 256              // 8 warps; 4 blocks/SM -> 512 blocks, 1 wave
#define FPB 128                  // frames per block
#define BPB (TT / FPB)           // 64 blocks per batch
#define GRID (BB * BPB)          // 512 blocks
#define FPW (FPB / (THREADS/32)) // 16 frames per warp

// Double-buffered published aggregates: low 32b = value, high 32b = flag.
// Statics zero-init, so parity 0 starts clean.
__device__ unsigned long long g_pubS1[2][GRID];
__device__ unsigned long long g_pubD[2][GRID];
__device__ int g_parity;
__device__ unsigned int g_done;

__device__ __forceinline__ void publish(unsigned long long* slot, float v) {
    *(volatile unsigned long long*)slot =
        (1ull << 32) | (unsigned long long)__float_as_uint(v);
}

// Warp-collective (warp 0): sum predecessor aggregates [0, kb), kb <= 63.
__device__ __forceinline__ float lookback(unsigned long long* base, int kb, int lane) {
    float v = 0.f;
#pragma unroll
    for (int k = 0; k < 2; k++) {
        const int idx = lane + k * 32;
        if (idx < kb) {
            unsigned long long u;
            do {
                u = *(volatile unsigned long long*)&base[idx];
            } while (!(u >> 32));
            v += __uint_as_float((unsigned)u);
        }
    }
#pragma unroll
    for (int o = 16; o > 0; o >>= 1) v += __shfl_xor_sync(0xffffffffu, v, o);
    return v;
}

__global__ void __launch_bounds__(THREADS, 4)
fused(const float* __restrict__ x, const float* __restrict__ w,
      float* __restrict__ out) {
    __shared__ float sS1[FPB];
    __shared__ float sQ[FPB];
    __shared__ float sI1[FPB];
    __shared__ float sID[FPB];
    __shared__ float sMean[FPB];
    __shared__ float sInv[FPB];
    __shared__ float sExcl1, sExclD;

    const int p = *(volatile int*)&g_parity;
    const int b = blockIdx.x / BPB;
    const int kb = blockIdx.x % BPB;
    const int wid = threadIdx.x >> 5;
    const int lane = threadIdx.x & 31;
    const size_t frame0 = (size_t)b * TT + (size_t)kb * FPB;

    // Clear the other parity's slots for the NEXT launch.
    if (threadIdx.x == 0) {
        *(volatile unsigned long long*)&g_pubS1[1 - p][blockIdx.x] = 0ull;
        *(volatile unsigned long long*)&g_pubD[1 - p][blockIdx.x] = 0ull;
    }

    // ---------------- Phase 1: 2-frame batched loads, per-frame reduce -----
    for (int j = 0; j < FPW; j += 2) {
        const int f = wid * FPW + j;
        const float4* p0 = reinterpret_cast<const float4*>(x + (frame0 + f) * CC);
        const float4* p1 = reinterpret_cast<const float4*>(x + (frame0 + f + 1) * CC);
        float4 a[4], c[4];
#pragma unroll
        for (int k = 0; k < 4; k++) a[k] = p0[lane + k * 32];
#pragma unroll
        for (int k = 0; k < 4; k++) c[k] = p1[lane + k * 32];

        float s0 = 0.f, q0 = 0.f, s1 = 0.f, q1 = 0.f;
#pragma unroll
        for (int k = 0; k < 4; k++) {
            s0 += (a[k].x + a[k].y) + (a[k].z + a[k].w);
            q0 += a[k].x * a[k].x + a[k].y * a[k].y + a[k].z * a[k].z + a[k].w * a[k].w;
            s1 += (c[k].x + c[k].y) + (c[k].z + c[k].w);
            q1 += c[k].x * c[k].x + c[k].y * c[k].y + c[k].z * c[k].z + c[k].w * c[k].w;
        }
#pragma unroll
        for (int o = 16; o > 0; o >>= 1) {
            s0 += __shfl_xor_sync(0xffffffffu, s0, o);
            q0 += __shfl_xor_sync(0xffffffffu, q0, o);
            s1 += __shfl_xor_sync(0xffffffffu, s1, o);
            q1 += __shfl_xor_sync(0xffffffffu, q1, o);
        }
        if (lane == 0) {
            sS1[f] = s0; sQ[f] = q0;
            sS1[f + 1] = s1; sQ[f + 1] = q1;
        }
    }
    __syncthreads();

    // ---------------- Block scan of S1 (warp 0, 4 values/lane) + lookback --
    if (wid == 0) {
        float v[4];
        float run = 0.f;
#pragma unroll
        for (int i = 0; i < 4; i++) { v[i] = sS1[lane * 4 + i]; run += v[i]; v[i] = run; }
        float incl = run;
#pragma unroll
        for (int o = 1; o < 32; o <<= 1) {
            float t = __shfl_up_sync(0xffffffffu, incl, o);
            if (lane >= o) incl += t;
        }
        float excl = incl - run;
#pragma unroll
        for (int i = 0; i < 4; i++) sI1[lane * 4 + i] = v[i] + excl;
        if (lane == 31) publish(&g_pubS1[p][blockIdx.x], incl);
        float e = lookback(&g_pubS1[p][b * BPB], kb, lane);
        if (lane == 0) sExcl1 = e;
    }
    __syncthreads();

    // ---------------- Phase 2a: per-frame mean and D -----------------------
    if (threadIdx.x < FPB) {
        const int t = kb * FPB + threadIdx.x;
        const float P = sExcl1 + sI1[threadIdx.x];
        const float cnt = (float)(t + 1) * (float)CC;
        const float m = P / cnt;
        sMean[threadIdx.x] = m;
        const float s1 = sS1[threadIdx.x];
        const float D = sQ[threadIdx.x] - 2.f * m * s1 + (float)CC * m * m;
        sQ[threadIdx.x] = D;  // reuse slot
    }
    __syncthreads();

    // ---------------- Block scan of D (warp 0) + lookback ------------------
    if (wid == 0) {
        float v[4];
        float run = 0.f;
#pragma unroll
        for (int i = 0; i < 4; i++) { v[i] = sQ[lane * 4 + i]; run += v[i]; v[i] = run; }
        float incl = run;
#pragma unroll
        for (int o = 1; o < 32; o <<= 1) {
            float t = __shfl_up_sync(0xffffffffu, incl, o);
            if (lane >= o) incl += t;
        }
        float excl = incl - run;
#pragma unroll
        for (int i = 0; i < 4; i++) sID[lane * 4 + i] = v[i] + excl;
        if (lane == 31) publish(&g_pubD[p][blockIdx.x], incl);
        float e = lookback(&g_pubD[p][b * BPB], kb, lane);
        if (lane == 0) sExclD = e;
    }
    __syncthreads();

    if (threadIdx.x < FPB) {
        const int t = kb * FPB + threadIdx.x;
        const float cnt = (float)(t + 1) * (float)CC;
        const float var = (sExclD + sID[threadIdx.x]) / cnt;
        sInv[threadIdx.x] = rsqrtf(var + EPSF);
    }
    __syncthreads();

    // ---------------- Phase 3: normalize, 2 frames per iteration -----------
    // __ldcs: re-read lines become evict-first after consumption so they do
    // not displace other blocks' pending re-reads. Forward streaming order.
    for (int j = 0; j < FPW; j += 2) {
        const int f = wid * FPW + j;
        const float m0 = sMean[f], iv0 = sInv[f];
        const float m1 = sMean[f + 1], iv1 = sInv[f + 1];
        const float4* p0 = reinterpret_cast<const float4*>(x + (frame0 + f) * CC);
        const float4* p1 = reinterpret_cast<const float4*>(x + (frame0 + f + 1) * CC);
        const float4* w4 = reinterpret_cast<const float4*>(w);
        float4* o0 = reinterpret_cast<float4*>(out + (frame0 + f) * CC);
        float4* o1 = reinterpret_cast<float4*>(out + (frame0 + f + 1) * CC);

        float4 a[4], c[4];
#pragma unroll
        for (int k = 0; k < 4; k++) a[k] = __ldcs(p0 + lane + k * 32);
#pragma unroll
        for (int k = 0; k < 4; k++) c[k] = __ldcs(p1 + lane + k * 32);

#pragma unroll
        for (int k = 0; k < 4; k++) {
            float4 wv = w4[lane + k * 32];  // L1-hot
            float4 r0, r1;
            r0.x = (a[k].x - m0) * iv0 * wv.x;
            r0.y = (a[k].y - m0) * iv0 * wv.y;
            r0.z = (a[k].z - m0) * iv0 * wv.z;
            r0.w = (a[k].w - m0) * iv0 * wv.w;
            r1.x = (c[k].x - m1) * iv1 * wv.x;
            r1.y = (c[k].y - m1) * iv1 * wv.y;
            r1.z = (c[k].z - m1) * iv1 * wv.z;
            r1.w = (c[k].w - m1) * iv1 * wv.w;
            __stcs(&o0[lane + k * 32], r0);
            __stcs(&o1[lane + k * 32], r1);
        }
    }

    // ---------------- Epilogue: last block flips parity --------------------
    __syncthreads();
    if (threadIdx.x == 0) {
        __threadfence();
        unsigned int n = atomicAdd(&g_done, 1u);
        if (n == GRID - 1) {
            g_done = 0;
            g_parity = p ^ 1;
        }
    }
}

extern "C" void kernel_launch(void* const* d_in, const int* in_sizes, int n_in,
                              void* d_out, int out_size) {
    const float* x = (const float*)d_in[0];
    const float* w = (const float*)d_in[1];
    float* out = (float*)d_out;
    fused<<<GRID, THREADS>>>(x, w, out);
}

// round 10
// speedup vs baseline: 1.5784x; 1.0160x over previous
#include <cuda_runtime.h>

// Shape fixed by setup_inputs: x [8, 8192, 512] fp32, weight [512] fp32.
#define BB 8
#define TT 8192
#define CC 512
#define EPSF 1e-5f

#define THREADS 256              // 8 warps; 4 blocks/SM -> 512 blocks, 1 wave
#define FPB 64                   // frames per tile
#define BPB (TT / FPB)           // 128 tiles per batch
#define NTILES (BB * TT / FPB)   // 1024 tiles
#define NBLK (NTILES / 2)        // 512 blocks, 2 tiles each
#define FPW (FPB / 8)            // 8 frames per warp per tile

// Double-buffered published aggregates: low 32b = value, high 32b = flag.
__device__ unsigned long long g_pubS1[2][NTILES];
__device__ unsigned long long g_pubD[2][NTILES];
__device__ int g_parity;
__device__ unsigned int g_done;

__device__ __forceinline__ void publish(unsigned long long* slot, float v) {
    *(volatile unsigned long long*)slot =
        (1ull << 32) | (unsigned long long)__float_as_uint(v);
}

// Warp-collective: sum predecessor aggregates [0, kb), kb <= 127 (4 slots/lane).
__device__ __forceinline__ float lookback(unsigned long long* base, int kb, int lane) {
    float v = 0.f;
#pragma unroll
    for (int k = 0; k < 4; k++) {
        const int idx = lane + k * 32;
        if (idx < kb) {
            unsigned long long u;
            do {
                u = *(volatile unsigned long long*)&base[idx];
            } while (!(u >> 32));
            v += __uint_as_float((unsigned)u);
        }
    }
#pragma unroll
    for (int o = 16; o > 0; o >>= 1) v += __shfl_xor_sync(0xffffffffu, v, o);
    return v;
}

// Inclusive warp scan.
__device__ __forceinline__ float warpscan(float v, int lane) {
#pragma unroll
    for (int o = 1; o < 32; o <<= 1) {
        float t = __shfl_up_sync(0xffffffffu, v, o);
        if (lane >= o) v += t;
    }
    return v;
}

// Phase 1: per-frame reductions for one tile (2-frame MLP batching).
__device__ __forceinline__ void reduce_tile(const float* __restrict__ x,
                                            size_t frame0, float* sS1, float* sQ,
                                            int wid, int lane) {
#pragma unroll
    for (int j = 0; j < FPW; j += 2) {
        const int f = wid * FPW + j;
        const float4* p0 = reinterpret_cast<const float4*>(x + (frame0 + f) * CC);
        const float4* p1 = reinterpret_cast<const float4*>(x + (frame0 + f + 1) * CC);
        float4 a[4], c[4];
#pragma unroll
        for (int k = 0; k < 4; k++) a[k] = p0[lane + k * 32];
#pragma unroll
        for (int k = 0; k < 4; k++) c[k] = p1[lane + k * 32];

        float s0 = 0.f, q0 = 0.f, s1 = 0.f, q1 = 0.f;
#pragma unroll
        for (int k = 0; k < 4; k++) {
            s0 += (a[k].x + a[k].y) + (a[k].z + a[k].w);
            q0 += a[k].x * a[k].x + a[k].y * a[k].y + a[k].z * a[k].z + a[k].w * a[k].w;
            s1 += (c[k].x + c[k].y) + (c[k].z + c[k].w);
            q1 += c[k].x * c[k].x + c[k].y * c[k].y + c[k].z * c[k].z + c[k].w * c[k].w;
        }
#pragma unroll
        for (int o = 16; o > 0; o >>= 1) {
            s0 += __shfl_xor_sync(0xffffffffu, s0, o);
            q0 += __shfl_xor_sync(0xffffffffu, q0, o);
            s1 += __shfl_xor_sync(0xffffffffu, s1, o);
            q1 += __shfl_xor_sync(0xffffffffu, q1, o);
        }
        if (lane == 0) {
            sS1[f] = s0; sQ[f] = q0;
            sS1[f + 1] = s1; sQ[f + 1] = q1;
        }
    }
}

// Warp 0: publish this tile's S1 block-aggregate (2 frames/lane).
__device__ __forceinline__ void scan_publish(int tile, int p, const float* sS1,
                                             int lane) {
    const float a0 = sS1[2 * lane];
    const float a1 = sS1[2 * lane + 1];
    const float incl = warpscan(a0 + a1, lane);
    if (lane == 31) publish(&g_pubS1[p][tile], incl);
}

// Warp 0: lookbacks + per-frame mean/inv for one tile.
__device__ __forceinline__ void stats(int tile, int p, int lane,
                                      const float* sS1, const float* sQ,
                                      float* sMean, float* sInv) {
    const int kb = tile % BPB;
    const int batch = tile / BPB;
    unsigned long long* baseS = &g_pubS1[p][batch * BPB];
    unsigned long long* baseD = &g_pubD[p][batch * BPB];

    const float a0 = sS1[2 * lane];
    const float a1 = sS1[2 * lane + 1];
    const float q0 = sQ[2 * lane];
    const float q1 = sQ[2 * lane + 1];

    const float pairsum = a0 + a1;
    const float incl = warpscan(pairsum, lane);
    const float exclL = incl - pairsum;

    const float exclB = lookback(baseS, kb, lane);

    const int t0 = kb * FPB + 2 * lane;
    const float c0 = (float)(t0 + 1) * (float)CC;
    const float c1 = (float)(t0 + 2) * (float)CC;
    const float m0 = (exclB + exclL + a0) / c0;
    const float m1 = (exclB + exclL + a0 + a1) / c1;

    const float D0 = q0 - 2.f * m0 * a0 + (float)CC * m0 * m0;
    const float D1 = q1 - 2.f * m1 * a1 + (float)CC * m1 * m1;
    const float dpair = D0 + D1;
    const float dincl = warpscan(dpair, lane);
    const float dexclL = dincl - dpair;
    if (lane == 31) publish(&g_pubD[p][tile], dincl);

    const float dexclB = lookback(baseD, kb, lane);

    const float v0 = (dexclB + dexclL + D0) / c0;
    const float v1 = (dexclB + dexclL + D0 + D1) / c1;
    sMean[2 * lane] = m0;
    sMean[2 * lane + 1] = m1;
    sInv[2 * lane] = rsqrtf(v0 + EPSF);
    sInv[2 * lane + 1] = rsqrtf(v1 + EPSF);
}

// Phase 3: normalize one tile (evict-first reads, streaming stores).
__device__ __forceinline__ void norm_tile(const float* __restrict__ x,
                                          const float* __restrict__ w,
                                          float* __restrict__ out, size_t frame0,
                                          const float* sMean, const float* sInv,
                                          int wid, int lane) {
#pragma unroll
    for (int j = 0; j < FPW; j += 2) {
        const int f = wid * FPW + j;
        const float m0 = sMean[f], iv0 = sInv[f];
        const float m1 = sMean[f + 1], iv1 = sInv[f + 1];
        const float4* p0 = reinterpret_cast<const float4*>(x + (frame0 + f) * CC);
        const float4* p1 = reinterpret_cast<const float4*>(x + (frame0 + f + 1) * CC);
        const float4* w4 = reinterpret_cast<const float4*>(w);
        float4* o0 = reinterpret_cast<float4*>(out + (frame0 + f) * CC);
        float4* o1 = reinterpret_cast<float4*>(out + (frame0 + f + 1) * CC);

        float4 a[4], c[4];
#pragma unroll
        for (int k = 0; k < 4; k++) a[k] = __ldcs(p0 + lane + k * 32);
#pragma unroll
        for (int k = 0; k < 4; k++) c[k] = __ldcs(p1 + lane + k * 32);

#pragma unroll
        for (int k = 0; k < 4; k++) {
            float4 wv = w4[lane + k * 32];  // L1-hot
            float4 r0, r1;
            r0.x = (a[k].x - m0) * iv0 * wv.x;
            r0.y = (a[k].y - m0) * iv0 * wv.y;
            r0.z = (a[k].z - m0) * iv0 * wv.z;
            r0.w = (a[k].w - m0) * iv0 * wv.w;
            r1.x = (c[k].x - m1) * iv1 * wv.x;
            r1.y = (c[k].y - m1) * iv1 * wv.y;
            r1.z = (c[k].z - m1) * iv1 * wv.z;
            r1.w = (c[k].w - m1) * iv1 * wv.w;
            __stcs(&o0[lane + k * 32], r0);
            __stcs(&o1[lane + k * 32], r1);
        }
    }
}

__global__ void __launch_bounds__(THREADS, 4)
fused(const float* __restrict__ x, const float* __restrict__ w,
      float* __restrict__ out) {
    __shared__ float sS1[2][FPB], sQ[2][FPB], sMean[2][FPB], sInv[2][FPB];

    const int p = *(volatile int*)&g_parity;
    const int wid = threadIdx.x >> 5;
    const int lane = threadIdx.x & 31;
    const int tileA = blockIdx.x;
    const int tileB = blockIdx.x + NBLK;
    const size_t f0A = (size_t)tileA * FPB;
    const size_t f0B = (size_t)tileB * FPB;

    // Clear the other parity's slots (both tiles) for the NEXT launch.
    if (threadIdx.x == 0) {
        *(volatile unsigned long long*)&g_pubS1[1 - p][tileA] = 0ull;
        *(volatile unsigned long long*)&g_pubD[1 - p][tileA] = 0ull;
        *(volatile unsigned long long*)&g_pubS1[1 - p][tileB] = 0ull;
        *(volatile unsigned long long*)&g_pubD[1 - p][tileB] = 0ull;
    }

    // -------- pipeline stage 1: reduce A, publish A, reduce B, publish B ---
    reduce_tile(x, f0A, sS1[0], sQ[0], wid, lane);
    __syncthreads();
    if (wid == 0) scan_publish(tileA, p, sS1[0], lane);
    reduce_tile(x, f0B, sS1[1], sQ[1], wid, lane);
    __syncthreads();
    if (wid == 0) {
        scan_publish(tileB, p, sS1[1], lane);
        // Join for tile A: predecessors published a full reduce-phase ago.
        stats(tileA, p, lane, sS1[0], sQ[0], sMean[0], sInv[0]);
    }
    __syncthreads();

    // -------- stage 2: warp 0 resolves B's join under A's normalize --------
    if (wid == 0) stats(tileB, p, lane, sS1[1], sQ[1], sMean[1], sInv[1]);
    norm_tile(x, w, out, f0A, sMean[0], sInv[0], wid, lane);
    __syncthreads();
    norm_tile(x, w, out, f0B, sMean[1], sInv[1], wid, lane);

    // -------- epilogue: last block flips parity ----------------------------
    __syncthreads();
    if (threadIdx.x == 0) {
        __threadfence();
        unsigned int n = atomicAdd(&g_done, 1u);
        if (n == NBLK - 1) {
            g_done = 0;
            g_parity = p ^ 1;
        }
    }
}

extern "C" void kernel_launch(void* const* d_in, const int* in_sizes, int n_in,
                              void* d_out, int out_size) {
    const float* x = (const float*)d_in[0];
    const float* w = (const float*)d_in[1];
    float* out = (float*)d_out;
    fused<<<NBLK, THREADS>>>(x, w, out);
}